// round 16
// baseline (speedup 1.0000x reference)
#include <cuda_runtime.h>
#include <cuda_fp16.h>
#include <cstdint>

// ---------------------------------------------------------------------------
// f16 2:4-sparse spline GEMM + dense fp16 silu GEMM, line-cut over 296 CTAs
// at 2 CTAs/SM: tile 128x128, warp tile 64x32, 3-buffer cp.async ring.
// Co-resident CTAs have independent barriers -> one CTA's barrier/wait window
// is covered by the other's mma issue (fixes the 43.5%-tensor ceiling of the
// single-CTA pipeline). RED.ADD tile-boundary flush into pre-zeroed C.
// ---------------------------------------------------------------------------

#define M_ROWS 4096
#define N_COLS 1024
#define BM 128
#define BN 128
#define NSPS 128
#define NSTG 144
#define NCTA 296

__device__ __align__(16) __half   g_A [(size_t)M_ROWS * 4096];
__device__ __align__(16) __half   g_As[(size_t)M_ROWS * 1024];
__device__ __align__(16) __half   g_B [(size_t)N_COLS * 8192];
__device__ __align__(16) __half   g_Bb[(size_t)N_COLS * 1024];
__device__ __align__(16) uint32_t g_M [(size_t)M_ROWS * 256];

__device__ __forceinline__ uint32_t smem_u32(const void* p) {
    uint32_t a;
    asm("{ .reg .u64 t; cvta.to.shared.u64 t, %1; cvt.u32.u64 %0, t; }"
        : "=r"(a) : "l"(p));
    return a;
}
__device__ __forceinline__ void cp_async16(uint32_t s, const void* g) {
    asm volatile("cp.async.cg.shared.global [%0], [%1], 16;" :: "r"(s), "l"(g));
}
__device__ __forceinline__ void cp_async8(uint32_t s, const void* g) {
    asm volatile("cp.async.ca.shared.global [%0], [%1], 8;" :: "r"(s), "l"(g));
}
__device__ __forceinline__ void ldmatrix_x4(uint32_t* r, uint32_t addr) {
    asm volatile("ldmatrix.sync.aligned.m8n8.x4.shared.b16 {%0,%1,%2,%3}, [%4];"
                 : "=r"(r[0]), "=r"(r[1]), "=r"(r[2]), "=r"(r[3]) : "r"(addr));
}
__device__ __forceinline__ void mma_sp_f16(float* d, const uint32_t* a,
                                           const uint32_t* b, uint32_t e) {
    asm volatile(
        "mma.sp::ordered_metadata.sync.aligned.m16n8k32.row.col.f32.f16.f16.f32 "
        "{%0,%1,%2,%3}, {%4,%5,%6,%7}, {%8,%9,%10,%11}, {%0,%1,%2,%3}, %12, 0x0;"
        : "+f"(d[0]), "+f"(d[1]), "+f"(d[2]), "+f"(d[3])
        : "r"(a[0]), "r"(a[1]), "r"(a[2]), "r"(a[3]),
          "r"(b[0]), "r"(b[1]), "r"(b[2]), "r"(b[3]), "r"(e));
}
__device__ __forceinline__ void mma16816(float* d, const uint32_t* a,
                                         const uint32_t* b) {
    asm volatile(
        "mma.sync.aligned.m16n8k16.row.col.f32.f16.f16.f32 "
        "{%0,%1,%2,%3}, {%4,%5,%6,%7}, {%8,%9}, {%0,%1,%2,%3};"
        : "+f"(d[0]), "+f"(d[1]), "+f"(d[2]), "+f"(d[3])
        : "r"(a[0]), "r"(a[1]), "r"(a[2]), "r"(a[3]), "r"(b[0]), "r"(b[1]));
}

__device__ __forceinline__ void spline_eval(float xv, uint32_t* hv,
                                            uint32_t& nibs) {
    int j = (int)floorf((xv + 2.2f) * 2.5f);
    bool ok = (j >= 0) && (j <= 10);
    float tj = (float)(j - 3) * 0.4f - 1.0f;
    float u  = (xv - tj) * 2.5f;
    float um = 1.0f - u;
    float u2 = u * u, u3 = u2 * u;
    float W0 = um * um * um * (1.0f / 6.0f);
    float W1 = (3.0f * u3 - 6.0f * u2 + 4.0f) * (1.0f / 6.0f);
    float W2 = (-3.0f * u3 + 3.0f * u2 + 3.0f * u + 1.0f) * (1.0f / 6.0f);
    float W3 = u3 * (1.0f / 6.0f);
    if (!ok) { W0 = W1 = W2 = W3 = 0.0f; }

    int   qe  = (j + 1) & 1;
    int   pe  = j - 3 + qe;
    float We0 = qe ? W1 : W0, We1 = qe ? W3 : W2;
    int   e0  = max(min(pe >> 1, 2), 0), e1 = e0 + 1;
    float ve0 = (2 * e0 == pe) ? We0 : ((2 * e0 == pe + 2) ? We1 : 0.0f);
    float ve1 = (2 * e1 == pe) ? We0 : ((2 * e1 == pe + 2) ? We1 : 0.0f);
    int   qo  = qe ^ 1;
    int   po  = j - 3 + qo;
    float Wo0 = qo ? W1 : W0, Wo1 = qo ? W3 : W2;
    int   o0  = max(min(po >> 1, 2), 0), o1 = o0 + 1;
    float vo0 = (2 * o0 + 1 == po) ? Wo0 : ((2 * o0 + 1 == po + 2) ? Wo1 : 0.0f);
    float vo1 = (2 * o1 + 1 == po) ? Wo0 : ((2 * o1 + 1 == po + 2) ? Wo1 : 0.0f);

    __half2 h0 = __floats2half2_rn(ve0, ve1);
    __half2 h1 = __floats2half2_rn(vo0, vo1);
    hv[0] = *(uint32_t*)&h0;
    hv[1] = *(uint32_t*)&h1;
    nibs = (uint32_t)(e0 | (e1 << 2)) | ((uint32_t)(o0 | (o1 << 2)) << 4);
}

// ---------------------------------------------------------------------------
// Prep (round-13, proven): blocks [0,8192) A-build + zero C; rest pack W.
// ---------------------------------------------------------------------------
__global__ void __launch_bounds__(256)
prep_kernel(const float* __restrict__ x,
            const float* __restrict__ bw,
            const float* __restrict__ sw,
            const float* __restrict__ ss,
            float* __restrict__ C) {
    const int t = threadIdx.x;
    if (blockIdx.x < 8192) {
        const int b = blockIdx.x >> 1;
        const int h = blockIdx.x & 1;
        const int i = h * 512 + 2 * t;

        *(float2*)&C[blockIdx.x * 512 + 2 * t] = make_float2(0.0f, 0.0f);

        float2 xv = *(const float2*)&x[b * 1024 + i];

        __half2 sl = __floats2half2_rn(xv.x / (1.0f + __expf(-xv.x)),
                                       xv.y / (1.0f + __expf(-xv.y)));
        *(uint32_t*)&g_As[(size_t)b * 1024 + i] = *(uint32_t*)&sl;

        uint32_t hv[4];
        uint32_t n0, n1;
        spline_eval(xv.x, hv,     n0);
        spline_eval(xv.y, hv + 2, n1);
        *(uint4*)(g_A + (size_t)b * 4096 + (size_t)i * 4) =
            make_uint4(hv[0], hv[1], hv[2], hv[3]);

        uint32_t my16 = n0 | (n1 << 8);
        uint32_t other = __shfl_down_sync(0xFFFFFFFFu, my16, 1);
        if (!(t & 1))
            g_M[(size_t)b * 256 + h * 128 + (t >> 1)] = my16 | (other << 16);
    } else {
        const int bid = blockIdx.x - 8192;
        const int o  = bid >> 2;
        const int i0 = (bid & 3) << 8;
        const int e  = o * 1024 + i0 + t;

        float sc = ss[e];
        const float* swp = sw + (size_t)e * 8;
        g_Bb[e] = __float2half(bw[e]);

        __half2 h[4];
        h[0] = __floats2half2_rn(swp[0] * sc, swp[2] * sc);
        h[1] = __floats2half2_rn(swp[4] * sc, swp[6] * sc);
        h[2] = __floats2half2_rn(swp[1] * sc, swp[3] * sc);
        h[3] = __floats2half2_rn(swp[5] * sc, swp[7] * sc);
        *(uint4*)(g_B + (size_t)o * 8192 + (size_t)(i0 + t) * 8) = *(uint4*)h;
    }
}

// ---------------------------------------------------------------------------
// GEMM: 296 CTAs (2/SM) x 256 threads, tile 128x128, warp tile 64x32,
// 3-buffer ring, one stage per barrier (cross-CTA overlap hides it).
// Work line: 256 tiles x 144 stages = 36864 units, tile t: mB=(t>>3)*128,
// nB=(t&7)*128.
// ---------------------------------------------------------------------------
#define STG_A (128 * 144)
#define STG_B (128 * 144)
#define STG_M 1024
#define STG   (STG_A + STG_M + STG_B)   // 37888
#define SMEM_TOT (3 * STG)              // 113664 (2 CTAs = 222 KB/SM)

__global__ void __launch_bounds__(256, 2)
gemm_kernel(float* __restrict__ C) {
    extern __shared__ char smc[];
    const uint32_t sb = smem_u32(smc);
    const int tid  = threadIdx.x;
    const int wid  = tid >> 5;
    const int lane = tid & 31;
    const int wm   = (wid >> 2) * 64;   // 0 / 64
    const int wn   = (wid & 3) * 32;    // 0..96

    const int r  = blockIdx.x;
    const int g0 = (4608 * r) / 37;        // 36864*r/296
    const int g1 = (4608 * (r + 1)) / 37;

    float acc[4][4][4];
#pragma unroll
    for (int mb = 0; mb < 4; mb++)
#pragma unroll
        for (int nb = 0; nb < 4; nb++)
#pragma unroll
            for (int q = 0; q < 4; q++) acc[mb][nb][q] = 0.0f;

#define PRE(buf, G)                                                            \
    do {                                                                       \
        int t2 = (G) / NSTG;                                                   \
        int ss = (G) - t2 * NSTG;                                              \
        int mB = (t2 >> 3) * BM;                                               \
        int nB = (t2 & 7) * BN;                                                \
        uint32_t d0 = sb + (buf) * STG;                                        \
        if (ss < NSPS) {                                                       \
            _Pragma("unroll")                                                  \
            for (int u = 0; u < 2; u++) {  /* A comp: 128 x 64B */             \
                int f = tid + u * 256, rr = f >> 2, q = f & 3;                 \
                cp_async16(d0 + rr * 144 + q * 16,                             \
                    (const char*)g_A + (size_t)(mB + rr) * 8192 +              \
                    ss * 64 + q * 16);                                         \
            }                                                                  \
            if (tid < 128)                 /* meta: 128 x 8B */                \
                cp_async8(d0 + STG_A + tid * 8,                                \
                    (const char*)g_M + (size_t)(mB + tid) * 1024 + ss * 8);    \
            _Pragma("unroll")                                                  \
            for (int u = 0; u < 4; u++) {  /* B: 128 x 128B */                 \
                int f = tid + u * 256, rr = f >> 3, q = f & 7;                 \
                cp_async16(d0 + STG_A + STG_M + rr * 144 + q * 16,             \
                    (const char*)g_B + (size_t)(nB + rr) * 16384 +             \
                    ss * 128 + q * 16);                                        \
            }                                                                  \
        } else {                                                               \
            int itd = ss - NSPS;                                               \
            _Pragma("unroll")                                                  \
            for (int u = 0; u < 4; u++) {  /* A silu: 128 x 128B */            \
                int f = tid + u * 256, rr = f >> 3, q = f & 7;                 \
                cp_async16(d0 + rr * 144 + q * 16,                             \
                    (const char*)g_As + (size_t)(mB + rr) * 2048 +             \
                    itd * 128 + q * 16);                                       \
            }                                                                  \
            _Pragma("unroll")                                                  \
            for (int u = 0; u < 4; u++) {  /* Bb: 128 x 128B */                \
                int f = tid + u * 256, rr = f >> 3, q = f & 7;                 \
                cp_async16(d0 + STG_A + STG_M + rr * 144 + q * 16,             \
                    (const char*)g_Bb + (size_t)(nB + rr) * 2048 +             \
                    itd * 128 + q * 16);                                       \
            }                                                                  \
        }                                                                      \
        asm volatile("cp.async.commit_group;" ::: "memory");                   \
    } while (0)

#define EPI_RED(tt)                                                            \
    do {                                                                       \
        int mB = ((tt) >> 3) * BM + wm + (lane >> 2);                          \
        int nB = ((tt) & 7) * BN + wn + (lane & 3) * 2;                        \
        _Pragma("unroll")                                                      \
        for (int mb = 0; mb < 4; mb++) {                                       \
            _Pragma("unroll")                                                  \
            for (int nb = 0; nb < 4; nb++) {                                   \
                int row = mB + mb * 16;                                        \
                int col = nB + nb * 8;                                         \
                atomicAdd(&C[(size_t)row * N_COLS + col],       acc[mb][nb][0]);\
                atomicAdd(&C[(size_t)row * N_COLS + col + 1],   acc[mb][nb][1]);\
                atomicAdd(&C[(size_t)(row + 8) * N_COLS + col],     acc[mb][nb][2]);\
                atomicAdd(&C[(size_t)(row + 8) * N_COLS + col + 1], acc[mb][nb][3]);\
                acc[mb][nb][0] = 0.0f; acc[mb][nb][1] = 0.0f;                  \
                acc[mb][nb][2] = 0.0f; acc[mb][nb][3] = 0.0f;                  \
            }                                                                  \
        }                                                                      \
    } while (0)

    PRE(0, g0);
    if (g0 + 1 < g1) PRE(1, g0 + 1);

    int buf = 0;
    for (int G = g0; G < g1; G++, buf = (buf == 2) ? 0 : buf + 1) {
        if (G + 1 < g1) {
            asm volatile("cp.async.wait_group 1;" ::: "memory");
        } else {
            asm volatile("cp.async.wait_group 0;" ::: "memory");
        }
        __syncthreads();

        if (G + 2 < g1) PRE((buf == 2) ? 1 : ((buf == 1) ? 0 : 2), G + 2);
        // ^ buffer (buf+2)%3: its readers (stage G-1) finished last iteration.

        const int t = G / NSTG;
        const int s = G - t * NSTG;
        if (s == 0 && G > g0) EPI_RED(t - 1);

        const uint32_t aB = sb + buf * STG;
        const uint32_t bB = aB + STG_A + STG_M;

        if (s < NSPS) {
            const char* mB = smc + buf * STG + STG_A;
#pragma unroll
            for (int c = 0; c < 2; c++) {
                uint32_t me[4];
#pragma unroll
                for (int mb = 0; mb < 4; mb++) {
                    int r0 = wm + mb * 16 + (lane >> 2);
                    uint32_t w0 = *(const uint32_t*)(mB + r0 * 8 + c * 4);
                    uint32_t w1 = *(const uint32_t*)(mB + (r0 + 8) * 8 + c * 4);
                    me[mb] = (lane & 1) ? ((w0 >> 16) | (w1 & 0xFFFF0000u))
                                        : ((w0 & 0xFFFFu) | (w1 << 16));
                }
                uint32_t a[4][4];
#pragma unroll
                for (int mb = 0; mb < 4; mb++)
                    ldmatrix_x4(a[mb], aB + (wm + mb * 16 + (lane & 15)) * 144
                                          + c * 32 + ((lane >> 4) << 4));
                uint32_t bq[4][4];
#pragma unroll
                for (int nb = 0; nb < 4; nb++)
                    ldmatrix_x4(bq[nb], bB + (wn + nb * 8 + (lane & 7)) * 144
                                           + c * 64 + ((lane >> 3) << 4));
#pragma unroll
                for (int mb = 0; mb < 4; mb++)
#pragma unroll
                    for (int nb = 0; nb < 4; nb++)
                        mma_sp_f16(acc[mb][nb], a[mb], bq[nb], me[mb]);
            }
        } else {
#pragma unroll
            for (int ks = 0; ks < 4; ks++) {
                uint32_t a[4][4], bf[4][2];
#pragma unroll
                for (int mb = 0; mb < 4; mb++)
                    ldmatrix_x4(a[mb], aB + (wm + mb * 16 + (lane & 15)) * 144
                                          + ks * 32 + ((lane >> 4) << 4));
#pragma unroll
                for (int np = 0; np < 2; np++) {
                    uint32_t q[4];
                    ldmatrix_x4(q, bB + (wn + np * 16 + (lane & 7)
                                         + ((lane >> 4) << 3)) * 144
                                      + ks * 32 + (((lane >> 3) & 1) << 4));
                    bf[np * 2][0] = q[0]; bf[np * 2][1] = q[1];
                    bf[np * 2 + 1][0] = q[2]; bf[np * 2 + 1][1] = q[3];
                }
#pragma unroll
                for (int mb = 0; mb < 4; mb++)
#pragma unroll
                    for (int nb = 0; nb < 4; nb++)
                        mma16816(acc[mb][nb], a[mb], bf[nb]);
            }
        }
    }

    EPI_RED((g1 - 1) / NSTG);
}

// ---------------------------------------------------------------------------
extern "C" void kernel_launch(void* const* d_in, const int* in_sizes, int n_in,
                              void* d_out, int out_size) {
    const float* x  = (const float*)d_in[0];
    const float* bw = (const float*)d_in[1];
    const float* sw = (const float*)d_in[2];
    const float* ss = (const float*)d_in[3];
    float* out = (float*)d_out;

    prep_kernel<<<12288, 256>>>(x, bw, sw, ss, out);

    cudaFuncSetAttribute(gemm_kernel,
                         cudaFuncAttributeMaxDynamicSharedMemorySize, SMEM_TOT);
    gemm_kernel<<<NCTA, 256, SMEM_TOT>>>(out);
}

// round 17
// speedup vs baseline: 1.1701x; 1.1701x over previous
#include <cuda_runtime.h>
#include <cuda_fp16.h>
#include <cstdint>

// ---------------------------------------------------------------------------
// Round-15 config (best: 205.5us) with intra-stage load/mma overlap:
// sparse stage loads BOTH chunks' A-fragments + metadata up front, then
// B-load(c) -> mma(c) with B registers reused across chunks, so chunk-1's
// ldmatrix issues under chunk-0's mma shadow. Paired-stage loop (one barrier
// per two stages), 4-buffer cp.async ring, line-cut over 148 CTAs, RED.ADD
// tile-boundary flush. Arithmetic order identical to round 15.
// ---------------------------------------------------------------------------

#define M_ROWS 4096
#define N_COLS 1024
#define BM 128
#define BN 256
#define NSPS 128
#define NSTG 144
#define NCTA 148

__device__ __align__(16) __half   g_A [(size_t)M_ROWS * 4096];
__device__ __align__(16) __half   g_As[(size_t)M_ROWS * 1024];
__device__ __align__(16) __half   g_B [(size_t)N_COLS * 8192];
__device__ __align__(16) __half   g_Bb[(size_t)N_COLS * 1024];
__device__ __align__(16) uint32_t g_M [(size_t)M_ROWS * 256];

__device__ __forceinline__ uint32_t smem_u32(const void* p) {
    uint32_t a;
    asm("{ .reg .u64 t; cvta.to.shared.u64 t, %1; cvt.u32.u64 %0, t; }"
        : "=r"(a) : "l"(p));
    return a;
}
__device__ __forceinline__ void cp_async16(uint32_t s, const void* g) {
    asm volatile("cp.async.cg.shared.global [%0], [%1], 16;" :: "r"(s), "l"(g));
}
__device__ __forceinline__ void cp_async8(uint32_t s, const void* g) {
    asm volatile("cp.async.ca.shared.global [%0], [%1], 8;" :: "r"(s), "l"(g));
}
__device__ __forceinline__ void ldmatrix_x4(uint32_t* r, uint32_t addr) {
    asm volatile("ldmatrix.sync.aligned.m8n8.x4.shared.b16 {%0,%1,%2,%3}, [%4];"
                 : "=r"(r[0]), "=r"(r[1]), "=r"(r[2]), "=r"(r[3]) : "r"(addr));
}
__device__ __forceinline__ void mma_sp_f16(float* d, const uint32_t* a,
                                           const uint32_t* b, uint32_t e) {
    asm volatile(
        "mma.sp::ordered_metadata.sync.aligned.m16n8k32.row.col.f32.f16.f16.f32 "
        "{%0,%1,%2,%3}, {%4,%5,%6,%7}, {%8,%9,%10,%11}, {%0,%1,%2,%3}, %12, 0x0;"
        : "+f"(d[0]), "+f"(d[1]), "+f"(d[2]), "+f"(d[3])
        : "r"(a[0]), "r"(a[1]), "r"(a[2]), "r"(a[3]),
          "r"(b[0]), "r"(b[1]), "r"(b[2]), "r"(b[3]), "r"(e));
}
__device__ __forceinline__ void mma16816(float* d, const uint32_t* a,
                                         const uint32_t* b) {
    asm volatile(
        "mma.sync.aligned.m16n8k16.row.col.f32.f16.f16.f32 "
        "{%0,%1,%2,%3}, {%4,%5,%6,%7}, {%8,%9}, {%0,%1,%2,%3};"
        : "+f"(d[0]), "+f"(d[1]), "+f"(d[2]), "+f"(d[3])
        : "r"(a[0]), "r"(a[1]), "r"(a[2]), "r"(a[3]), "r"(b[0]), "r"(b[1]));
}

__device__ __forceinline__ void spline_eval(float xv, uint32_t* hv,
                                            uint32_t& nibs) {
    int j = (int)floorf((xv + 2.2f) * 2.5f);
    bool ok = (j >= 0) && (j <= 10);
    float tj = (float)(j - 3) * 0.4f - 1.0f;
    float u  = (xv - tj) * 2.5f;
    float um = 1.0f - u;
    float u2 = u * u, u3 = u2 * u;
    float W0 = um * um * um * (1.0f / 6.0f);
    float W1 = (3.0f * u3 - 6.0f * u2 + 4.0f) * (1.0f / 6.0f);
    float W2 = (-3.0f * u3 + 3.0f * u2 + 3.0f * u + 1.0f) * (1.0f / 6.0f);
    float W3 = u3 * (1.0f / 6.0f);
    if (!ok) { W0 = W1 = W2 = W3 = 0.0f; }

    int   qe  = (j + 1) & 1;
    int   pe  = j - 3 + qe;
    float We0 = qe ? W1 : W0, We1 = qe ? W3 : W2;
    int   e0  = max(min(pe >> 1, 2), 0), e1 = e0 + 1;
    float ve0 = (2 * e0 == pe) ? We0 : ((2 * e0 == pe + 2) ? We1 : 0.0f);
    float ve1 = (2 * e1 == pe) ? We0 : ((2 * e1 == pe + 2) ? We1 : 0.0f);
    int   qo  = qe ^ 1;
    int   po  = j - 3 + qo;
    float Wo0 = qo ? W1 : W0, Wo1 = qo ? W3 : W2;
    int   o0  = max(min(po >> 1, 2), 0), o1 = o0 + 1;
    float vo0 = (2 * o0 + 1 == po) ? Wo0 : ((2 * o0 + 1 == po + 2) ? Wo1 : 0.0f);
    float vo1 = (2 * o1 + 1 == po) ? Wo0 : ((2 * o1 + 1 == po + 2) ? Wo1 : 0.0f);

    __half2 h0 = __floats2half2_rn(ve0, ve1);
    __half2 h1 = __floats2half2_rn(vo0, vo1);
    hv[0] = *(uint32_t*)&h0;
    hv[1] = *(uint32_t*)&h1;
    nibs = (uint32_t)(e0 | (e1 << 2)) | ((uint32_t)(o0 | (o1 << 2)) << 4);
}

// ---------------------------------------------------------------------------
// Prep (proven): blocks [0,8192) A-build + zero C; blocks [8192,12288) pack W.
// ---------------------------------------------------------------------------
__global__ void __launch_bounds__(256)
prep_kernel(const float* __restrict__ x,
            const float* __restrict__ bw,
            const float* __restrict__ sw,
            const float* __restrict__ ss,
            float* __restrict__ C) {
    const int t = threadIdx.x;
    if (blockIdx.x < 8192) {
        const int b = blockIdx.x >> 1;
        const int h = blockIdx.x & 1;
        const int i = h * 512 + 2 * t;

        *(float2*)&C[blockIdx.x * 512 + 2 * t] = make_float2(0.0f, 0.0f);

        float2 xv = *(const float2*)&x[b * 1024 + i];

        __half2 sl = __floats2half2_rn(xv.x / (1.0f + __expf(-xv.x)),
                                       xv.y / (1.0f + __expf(-xv.y)));
        *(uint32_t*)&g_As[(size_t)b * 1024 + i] = *(uint32_t*)&sl;

        uint32_t hv[4];
        uint32_t n0, n1;
        spline_eval(xv.x, hv,     n0);
        spline_eval(xv.y, hv + 2, n1);
        *(uint4*)(g_A + (size_t)b * 4096 + (size_t)i * 4) =
            make_uint4(hv[0], hv[1], hv[2], hv[3]);

        uint32_t my16 = n0 | (n1 << 8);
        uint32_t other = __shfl_down_sync(0xFFFFFFFFu, my16, 1);
        if (!(t & 1))
            g_M[(size_t)b * 256 + h * 128 + (t >> 1)] = my16 | (other << 16);
    } else {
        const int bid = blockIdx.x - 8192;
        const int o  = bid >> 2;
        const int i0 = (bid & 3) << 8;
        const int e  = o * 1024 + i0 + t;

        float sc = ss[e];
        const float* swp = sw + (size_t)e * 8;
        g_Bb[e] = __float2half(bw[e]);

        __half2 h[4];
        h[0] = __floats2half2_rn(swp[0] * sc, swp[2] * sc);
        h[1] = __floats2half2_rn(swp[4] * sc, swp[6] * sc);
        h[2] = __floats2half2_rn(swp[1] * sc, swp[3] * sc);
        h[3] = __floats2half2_rn(swp[5] * sc, swp[7] * sc);
        *(uint4*)(g_B + (size_t)o * 8192 + (size_t)(i0 + t) * 8) = *(uint4*)h;
    }
}

// ---------------------------------------------------------------------------
// GEMM: 148 CTAs x 256 threads, line-cut, 4-buffer ring, paired stages.
// ---------------------------------------------------------------------------
#define STG_A (128 * 144)
#define STG_B (256 * 144)
#define STG_M 1024
#define STG   (STG_A + STG_B + STG_M)   // 56320
#define SMEM_TOT (4 * STG)              // 225280

__global__ void __launch_bounds__(256, 1)
gemm_kernel(float* __restrict__ C) {
    extern __shared__ char smc[];
    const uint32_t sb = smem_u32(smc);
    const int tid  = threadIdx.x;
    const int wid  = tid >> 5;
    const int lane = tid & 31;
    const int wm   = (wid >> 2) * 64;
    const int wn   = (wid & 3) * 64;

    const int r  = blockIdx.x;
    const int g0 = (4608 * r) / 37;
    const int g1 = (4608 * (r + 1)) / 37;

    float acc[4][8][4];
#pragma unroll
    for (int mb = 0; mb < 4; mb++)
#pragma unroll
        for (int nb = 0; nb < 8; nb++)
#pragma unroll
            for (int q = 0; q < 4; q++) acc[mb][nb][q] = 0.0f;

#define PRE(buf, G)                                                            \
    do {                                                                       \
        int t2 = (G) / NSTG;                                                   \
        int ss = (G) - t2 * NSTG;                                              \
        int mB = (t2 >> 2) * BM;                                               \
        int nB = (t2 & 3) * BN;                                                \
        uint32_t d0 = sb + (buf) * STG;                                        \
        if (ss < NSPS) {                                                       \
            _Pragma("unroll")                                                  \
            for (int u = 0; u < 2; u++) {                                      \
                int f = tid + u * 256, rr = f >> 2, q = f & 3;                 \
                cp_async16(d0 + rr * 144 + q * 16,                             \
                    (const char*)g_A + (size_t)(mB + rr) * 8192 +              \
                    ss * 64 + q * 16);                                         \
            }                                                                  \
            _Pragma("unroll")                                                  \
            for (int u = 0; u < 8; u++) {                                      \
                int f = tid + u * 256, rr = f >> 3, q = f & 7;                 \
                cp_async16(d0 + STG_A + rr * 144 + q * 16,                     \
                    (const char*)g_B + (size_t)(nB + rr) * 16384 +             \
                    ss * 128 + q * 16);                                        \
            }                                                                  \
            if (tid < 128)                                                     \
                cp_async8(d0 + STG_A + STG_B + tid * 8,                        \
                    (const char*)g_M + (size_t)(mB + tid) * 1024 + ss * 8);    \
        } else {                                                               \
            int itd = ss - NSPS;                                               \
            _Pragma("unroll")                                                  \
            for (int u = 0; u < 4; u++) {                                      \
                int f = tid + u * 256, rr = f >> 3, q = f & 7;                 \
                cp_async16(d0 + rr * 144 + q * 16,                             \
                    (const char*)g_As + (size_t)(mB + rr) * 2048 +             \
                    itd * 128 + q * 16);                                       \
            }                                                                  \
            _Pragma("unroll")                                                  \
            for (int u = 0; u < 8; u++) {                                      \
                int f = tid + u * 256, rr = f >> 3, q = f & 7;                 \
                cp_async16(d0 + STG_A + rr * 144 + q * 16,                     \
                    (const char*)g_Bb + (size_t)(nB + rr) * 2048 +             \
                    itd * 128 + q * 16);                                       \
            }                                                                  \
        }                                                                      \
        asm volatile("cp.async.commit_group;" ::: "memory");                   \
    } while (0)

#define EPI_RED(tt)                                                            \
    do {                                                                       \
        int mB = ((tt) >> 2) * BM + wm + (lane >> 2);                          \
        int nB = ((tt) & 3) * BN + wn + (lane & 3) * 2;                        \
        _Pragma("unroll")                                                      \
        for (int mb = 0; mb < 4; mb++) {                                       \
            _Pragma("unroll")                                                  \
            for (int nb = 0; nb < 8; nb++) {                                   \
                int row = mB + mb * 16;                                        \
                int col = nB + nb * 8;                                         \
                atomicAdd(&C[(size_t)row * N_COLS + col],       acc[mb][nb][0]);\
                atomicAdd(&C[(size_t)row * N_COLS + col + 1],   acc[mb][nb][1]);\
                atomicAdd(&C[(size_t)(row + 8) * N_COLS + col],     acc[mb][nb][2]);\
                atomicAdd(&C[(size_t)(row + 8) * N_COLS + col + 1], acc[mb][nb][3]);\
                acc[mb][nb][0] = 0.0f; acc[mb][nb][1] = 0.0f;                  \
                acc[mb][nb][2] = 0.0f; acc[mb][nb][3] = 0.0f;                  \
            }                                                                  \
        }                                                                      \
    } while (0)

// Sparse stage, overlapped: A+meta for BOTH chunks loaded up front; B regs
// reused across chunks so chunk-1 B ldmatrix issues under chunk-0 mma shadow.
// mma issue order (c, mb, nb) identical to round 15.
#define DO_STAGE(GG)                                                           \
    do {                                                                       \
        const int t_ = (GG) / NSTG;                                            \
        const int s_ = (GG) - t_ * NSTG;                                       \
        if (s_ == 0 && (GG) > g0) EPI_RED(t_ - 1);                             \
        const int buf_ = ((GG) - g0) & 3;                                      \
        const uint32_t aB = sb + buf_ * STG;                                   \
        const uint32_t bB = aB + STG_A;                                        \
        if (s_ < NSPS) {                                                       \
            const char* mB = smc + buf_ * STG + STG_A + STG_B;                 \
            uint32_t me[2][4];                                                 \
            uint32_t a2[2][4][4];                                              \
            _Pragma("unroll")                                                  \
            for (int c = 0; c < 2; c++) {                                      \
                _Pragma("unroll")                                              \
                for (int mb = 0; mb < 4; mb++) {                               \
                    int r0 = wm + mb * 16 + (lane >> 2);                       \
                    uint32_t w0 = *(const uint32_t*)(mB + r0 * 8 + c * 4);     \
                    uint32_t w1 = *(const uint32_t*)(mB + (r0 + 8) * 8 + c * 4);\
                    me[c][mb] = (lane & 1) ? ((w0 >> 16) | (w1 & 0xFFFF0000u)) \
                                           : ((w0 & 0xFFFFu) | (w1 << 16));    \
                }                                                              \
                _Pragma("unroll")                                              \
                for (int mb = 0; mb < 4; mb++)                                 \
                    ldmatrix_x4(a2[c][mb],                                     \
                        aB + (wm + mb * 16 + (lane & 15)) * 144                \
                           + c * 32 + ((lane >> 4) << 4));                     \
            }                                                                  \
            uint32_t bq[8][4];                                                 \
            _Pragma("unroll")                                                  \
            for (int c = 0; c < 2; c++) {                                      \
                _Pragma("unroll")                                              \
                for (int nb = 0; nb < 8; nb++)                                 \
                    ldmatrix_x4(bq[nb],                                        \
                        bB + (wn + nb * 8 + (lane & 7)) * 144                  \
                           + c * 64 + ((lane >> 3) << 4));                     \
                _Pragma("unroll")                                              \
                for (int mb = 0; mb < 4; mb++)                                 \
                    _Pragma("unroll")                                          \
                    for (int nb = 0; nb < 8; nb++)                             \
                        mma_sp_f16(acc[mb][nb], a2[c][mb], bq[nb], me[c][mb]); \
            }                                                                  \
        } else {                                                               \
            _Pragma("unroll")                                                  \
            for (int ks = 0; ks < 4; ks++) {                                   \
                uint32_t a[4][4], bf[8][2];                                    \
                _Pragma("unroll")                                              \
                for (int mb = 0; mb < 4; mb++)                                 \
                    ldmatrix_x4(a[mb],                                         \
                        aB + (wm + mb * 16 + (lane & 15)) * 144                \
                           + ks * 32 + ((lane >> 4) << 4));                    \
                _Pragma("unroll")                                              \
                for (int np = 0; np < 4; np++) {                               \
                    uint32_t q[4];                                             \
                    ldmatrix_x4(q,                                             \
                        bB + (wn + np * 16 + (lane & 7)                        \
                              + ((lane >> 4) << 3)) * 144                      \
                           + ks * 32 + (((lane >> 3) & 1) << 4));              \
                    bf[np * 2][0] = q[0]; bf[np * 2][1] = q[1];                \
                    bf[np * 2 + 1][0] = q[2]; bf[np * 2 + 1][1] = q[3];        \
                }                                                              \
                _Pragma("unroll")                                              \
                for (int mb = 0; mb < 4; mb++)                                 \
                    _Pragma("unroll")                                          \
                    for (int nb = 0; nb < 8; nb++)                             \
                        mma16816(acc[mb][nb], a[mb], bf[nb]);                  \
            }                                                                  \
        }                                                                      \
    } while (0)

    PRE(0, g0);
    if (g0 + 1 < g1) PRE(1, g0 + 1);

    for (int G = g0; G < g1; G += 2) {
        asm volatile("cp.async.wait_group 0;" ::: "memory");
        __syncthreads();

        if (G + 2 < g1) PRE((G + 2 - g0) & 3, G + 2);
        if (G + 3 < g1) PRE((G + 3 - g0) & 3, G + 3);

        DO_STAGE(G);
        if (G + 1 < g1) DO_STAGE(G + 1);
    }

    EPI_RED((g1 - 1) / NSTG);
}

// ---------------------------------------------------------------------------
extern "C" void kernel_launch(void* const* d_in, const int* in_sizes, int n_in,
                              void* d_out, int out_size) {
    const float* x  = (const float*)d_in[0];
    const float* bw = (const float*)d_in[1];
    const float* sw = (const float*)d_in[2];
    const float* ss = (const float*)d_in[3];
    float* out = (float*)d_out;

    prep_kernel<<<12288, 256>>>(x, bw, sw, ss, out);

    cudaFuncSetAttribute(gemm_kernel,
                         cudaFuncAttributeMaxDynamicSharedMemorySize, SMEM_TOT);
    gemm_kernel<<<NCTA, 256, SMEM_TOT>>>(out);
}